// round 4
// baseline (speedup 1.0000x reference)
#include <cuda_runtime.h>

// Shapes (fixed by the problem)
#define Bb 256
#define Cc 256
#define CH 128
#define NN 196               // H*W = 14*14
#define N4 49                // float4s per channel row
#define TOT_F4 (Bb * Cc * N4)   // 3,211,264
#define EPS 1e-5f

// K1 geometry: 8 blocks per batch, 512 thr, warp handles 2 adjacent rows.
#define K1_BLOCKS_PER_B 8
#define K1_BLOCKS (Bb * K1_BLOCKS_PER_B)   // 2048

// K2 geometry: exact tiling, no bounds checks.
// 1568 blocks * 512 threads * 4 f4/thread = 3,211,264 = TOT_F4
#define K2_BLOCKS 1568
#define K2_THREADS 512
#define K2_STRIDE (K2_BLOCKS * K2_THREADS)

__device__ float g_ysum[Bb * Cc];   // per-(b,c) spatial sum of y
__device__ float g_zbn[Bb * Cc];    // per-(b,o) BN-folded bias term
__device__ int   g_cnt[Bb];         // per-batch completion counters (winner resets)

// ---------------------------------------------------------------------------
// K1: streaming y-reduction + last-block-per-batch projection.
//   Softmax over singleton axis == 1 => attention collapses to spatial sum;
//   Wq, Wk are mathematically dead.
//   zbn[b,o] = BN( Wz[o,:] @ (Wv @ ysum[b,:]) )
// ---------------------------------------------------------------------------
__global__ void __launch_bounds__(512)
k_zbn(const float* __restrict__ y,
      const float* __restrict__ Wv,
      const float* __restrict__ Wz,
      const float* __restrict__ bn_w,
      const float* __restrict__ bn_b,
      const float* __restrict__ bn_m,
      const float* __restrict__ bn_v) {
    __shared__ float ys[Cc];
    __shared__ float tmp[CH];
    __shared__ int   s_last;

    const int b    = blockIdx.x >> 3;           // batch
    const int rg   = blockIdx.x & 7;            // row-group within batch
    const int t    = threadIdx.x;
    const int warp = t >> 5;                    // 0..15
    const int lane = t & 31;

    // ---- streaming phase: warp reduces 2 adjacent rows (4 front loads) ----
    const int row0 = b * Cc + rg * 32 + warp * 2;   // global (b,c) row index
    const float4* r0 = reinterpret_cast<const float4*>(y) + (size_t)row0 * N4;
    const float4* r1 = r0 + N4;

    float4 a0 = __ldcs(&r0[lane]);
    float4 a1 = (lane < N4 - 32) ? __ldcs(&r0[lane + 32]) : make_float4(0,0,0,0);
    float4 b0 = __ldcs(&r1[lane]);
    float4 b1 = (lane < N4 - 32) ? __ldcs(&r1[lane + 32]) : make_float4(0,0,0,0);

    float s0 = a0.x + a0.y + a0.z + a0.w + a1.x + a1.y + a1.z + a1.w;
    float s1 = b0.x + b0.y + b0.z + b0.w + b1.x + b1.y + b1.z + b1.w;
    #pragma unroll
    for (int o = 16; o; o >>= 1) {
        s0 += __shfl_xor_sync(0xFFFFFFFFu, s0, o);
        s1 += __shfl_xor_sync(0xFFFFFFFFu, s1, o);
    }
    if (lane == 0) {
        g_ysum[row0]     = s0;
        g_ysum[row0 + 1] = s1;
        __threadfence();                        // publish before the atomic
    }
    __syncthreads();

    // ---- last block of this batch wins and does the projection ----
    if (t == 0) {
        int old = atomicAdd(&g_cnt[b], 1);
        s_last = (old == K1_BLOCKS_PER_B - 1);
        if (s_last) g_cnt[b] = 0;               // reset for next graph replay
    }
    __syncthreads();
    if (!s_last) return;
    __threadfence();                            // acquire published sums

    // load this batch's 256 sums into smem
    if (t < Cc) ys[t] = g_ysum[b * Cc + t];
    __syncthreads();

    // Phase A: tmp[ch] = Wv[ch,:] . ys   (128 ch x 4 parts = 512 thr)
    {
        const int ch = t >> 2, part = t & 3;
        const float4* wr = reinterpret_cast<const float4*>(Wv + ch * Cc) + part * 16;
        const float* yss = ys + part * 64;
        float acc = 0.0f;
        #pragma unroll
        for (int i = 0; i < 16; i++) {
            float4 v = wr[i];
            acc += v.x * yss[4*i]   + v.y * yss[4*i+1]
                 + v.z * yss[4*i+2] + v.w * yss[4*i+3];
        }
        acc += __shfl_xor_sync(0xFFFFFFFFu, acc, 1);
        acc += __shfl_xor_sync(0xFFFFFFFFu, acc, 2);
        if (part == 0) tmp[ch] = acc;
    }
    __syncthreads();

    // Phase B: z[o] = Wz[o,:] . tmp, BN fold   (256 o x 2 parts = 512 thr)
    {
        const int o = t >> 1, part = t & 1;
        const float4* wr = reinterpret_cast<const float4*>(Wz + o * CH) + part * 16;
        const float* tp = tmp + part * 64;
        float acc = 0.0f;
        #pragma unroll
        for (int i = 0; i < 16; i++) {
            float4 v = wr[i];
            acc += v.x * tp[4*i]   + v.y * tp[4*i+1]
                 + v.z * tp[4*i+2] + v.w * tp[4*i+3];
        }
        acc += __shfl_xor_sync(0xFFFFFFFFu, acc, 1);
        if (part == 0) {
            const float inv = rsqrtf(bn_v[o] + EPS);
            g_zbn[b * Cc + o] = (acc - bn_m[o]) * inv * bn_w[o] + bn_b[o];
        }
    }
    // kernel completion releases the PDL dependency for K2
}

// ---------------------------------------------------------------------------
// K2: out[i] = x[i] + zbn[i / 49] over float4s.
// Front-batches 4 independent LDG.128 BEFORE the PDL sync so x-streaming
// overlaps K1's tail. Exact tiling -> no bounds checks. Streaming hints:
// x and out are touched exactly once.
// ---------------------------------------------------------------------------
__global__ void __launch_bounds__(K2_THREADS)
k_out(const float* __restrict__ x, float* __restrict__ out) {
    const int tid = blockIdx.x * K2_THREADS + threadIdx.x;
    const float4* x4 = reinterpret_cast<const float4*>(x);
    float4*       o4 = reinterpret_cast<float4*>(out);

    float4 v0 = __ldcs(&x4[tid + 0 * K2_STRIDE]);
    float4 v1 = __ldcs(&x4[tid + 1 * K2_STRIDE]);
    float4 v2 = __ldcs(&x4[tid + 2 * K2_STRIDE]);
    float4 v3 = __ldcs(&x4[tid + 3 * K2_STRIDE]);

    cudaGridDependencySynchronize();            // wait for K1's zbn

    const float z0 = __ldg(&g_zbn[(tid + 0 * K2_STRIDE) / N4]);
    const float z1 = __ldg(&g_zbn[(tid + 1 * K2_STRIDE) / N4]);
    const float z2 = __ldg(&g_zbn[(tid + 2 * K2_STRIDE) / N4]);
    const float z3 = __ldg(&g_zbn[(tid + 3 * K2_STRIDE) / N4]);

    v0.x += z0; v0.y += z0; v0.z += z0; v0.w += z0;
    v1.x += z1; v1.y += z1; v1.z += z1; v1.w += z1;
    v2.x += z2; v2.y += z2; v2.z += z2; v2.w += z2;
    v3.x += z3; v3.y += z3; v3.z += z3; v3.w += z3;

    __stcs(&o4[tid + 0 * K2_STRIDE], v0);
    __stcs(&o4[tid + 1 * K2_STRIDE], v1);
    __stcs(&o4[tid + 2 * K2_STRIDE], v2);
    __stcs(&o4[tid + 3 * K2_STRIDE], v3);
}

// ---------------------------------------------------------------------------
// Inputs (metadata order):
//  0:x 1:y 2:Wq 3:Wk 4:Wv 5:Wz 6:bn_weight 7:bn_bias 8:bn_mean 9:bn_var
// ---------------------------------------------------------------------------
extern "C" void kernel_launch(void* const* d_in, const int* in_sizes, int n_in,
                              void* d_out, int out_size) {
    const float* x    = (const float*)d_in[0];
    const float* y    = (const float*)d_in[1];
    const float* Wv   = (const float*)d_in[4];
    const float* Wz   = (const float*)d_in[5];
    const float* bn_w = (const float*)d_in[6];
    const float* bn_b = (const float*)d_in[7];
    const float* bn_m = (const float*)d_in[8];
    const float* bn_v = (const float*)d_in[9];
    float* out = (float*)d_out;

    k_zbn<<<K1_BLOCKS, 512>>>(y, Wv, Wz, bn_w, bn_b, bn_m, bn_v);

    // PDL: K2 may dispatch while K1 runs; cudaGridDependencySynchronize()
    // inside K2 gates the zbn reads on K1 completion.
    cudaLaunchConfig_t cfg = {};
    cfg.gridDim  = dim3(K2_BLOCKS, 1, 1);
    cfg.blockDim = dim3(K2_THREADS, 1, 1);
    cudaLaunchAttribute attr[1];
    attr[0].id = cudaLaunchAttributeProgrammaticStreamSerialization;
    attr[0].val.programmaticStreamSerializationAllowed = 1;
    cfg.attrs = attr;
    cfg.numAttrs = 1;
    cudaLaunchKernelEx(&cfg, k_out, x, out);
}

// round 5
// speedup vs baseline: 1.2981x; 1.2981x over previous
#include <cuda_runtime.h>

// Shapes (fixed by the problem)
#define Bb 256
#define Cc 256
#define CH 128
#define NN 196               // H*W = 14*14
#define N4 49                // float4s per channel row
#define TOT_F4 (Bb * Cc * N4)   // 3,211,264
#define EPS 1e-5f

// K3 geometry: exact tiling, no bounds checks.
// 1568 blocks * 512 threads * 4 f4/thread = 3,211,264 = TOT_F4
#define K3_BLOCKS 1568
#define K3_THREADS 512
#define K3_STRIDE (K3_BLOCKS * K3_THREADS)

__device__ float g_ysum[Bb * Cc];   // per-(b,c) spatial sum of y
__device__ float g_zbn[Bb * Cc];    // per-(b,o) BN-folded bias term

// ---------------------------------------------------------------------------
// K1: ysum[b,c] = sum_n y[b,c,n].
// One warp per 2 adjacent rows, 4 front-batched LDG.128 (MLP=4).
// 65536 rows -> 32768 warps -> 4096 blocks of 256 threads.
// ---------------------------------------------------------------------------
__global__ void __launch_bounds__(256)
k_ysum(const float* __restrict__ y) {
    const int gw   = (blockIdx.x * 256 + threadIdx.x) >> 5;  // global warp
    const int lane = threadIdx.x & 31;
    const int row0 = gw * 2;                                  // (b,c) row pair

    const float4* r0 = reinterpret_cast<const float4*>(y) + (size_t)row0 * N4;
    const float4* r1 = r0 + N4;

    float4 a0 = r0[lane];
    float4 a1 = (lane < N4 - 32) ? r0[lane + 32] : make_float4(0,0,0,0);
    float4 b0 = r1[lane];
    float4 b1 = (lane < N4 - 32) ? r1[lane + 32] : make_float4(0,0,0,0);

    float s0 = a0.x + a0.y + a0.z + a0.w + a1.x + a1.y + a1.z + a1.w;
    float s1 = b0.x + b0.y + b0.z + b0.w + b1.x + b1.y + b1.z + b1.w;
    #pragma unroll
    for (int o = 16; o; o >>= 1) {
        s0 += __shfl_xor_sync(0xFFFFFFFFu, s0, o);
        s1 += __shfl_xor_sync(0xFFFFFFFFu, s1, o);
    }
    if (lane == 0) g_ysum[row0]     = s0;
    if (lane == 1) g_ysum[row0 + 1] = s1;   // s1 is uniform post-reduction
}

// ---------------------------------------------------------------------------
// K2: per batch b (one 256-thread block):
//   tmp = Wv @ ysum[b,:]   (softmax over singleton axis == 1 => collapse;
//   z   = Wz @ tmp          Wq, Wk are mathematically dead)
//   zbn = BN fold
// ---------------------------------------------------------------------------
__global__ void __launch_bounds__(256)
k_proj(const float* __restrict__ Wv,
       const float* __restrict__ Wz,
       const float* __restrict__ bn_w,
       const float* __restrict__ bn_b,
       const float* __restrict__ bn_m,
       const float* __restrict__ bn_v) {
    __shared__ float ys[Cc];
    __shared__ float tmp[CH];
    const int b = blockIdx.x;
    const int t = threadIdx.x;

    ys[t] = g_ysum[b * Cc + t];
    __syncthreads();

    if (t < CH) {
        const float4* wr = reinterpret_cast<const float4*>(Wv + t * Cc);
        float acc = 0.0f;
        #pragma unroll
        for (int i = 0; i < Cc / 4; i++) {
            float4 v = wr[i];
            acc += v.x * ys[4*i]   + v.y * ys[4*i+1]
                 + v.z * ys[4*i+2] + v.w * ys[4*i+3];
        }
        tmp[t] = acc;
    }
    __syncthreads();

    {
        const float4* wr = reinterpret_cast<const float4*>(Wz + t * CH);
        float acc = 0.0f;
        #pragma unroll
        for (int i = 0; i < CH / 4; i++) {
            float4 v = wr[i];
            acc += v.x * tmp[4*i]   + v.y * tmp[4*i+1]
                 + v.z * tmp[4*i+2] + v.w * tmp[4*i+3];
        }
        const float inv = rsqrtf(bn_v[t] + EPS);
        g_zbn[b * Cc + t] = (acc - bn_m[t]) * inv * bn_w[t] + bn_b[t];
    }
}

// ---------------------------------------------------------------------------
// K3: out[i] = x[i] + zbn[i / 49] over float4s.
// 4 independent front-batched LDG.128 per thread; exact tiling, no bounds
// checks. (Known-good: 15.2us standalone.)
// ---------------------------------------------------------------------------
__global__ void __launch_bounds__(K3_THREADS)
k_out(const float* __restrict__ x, float* __restrict__ out) {
    const int tid = blockIdx.x * K3_THREADS + threadIdx.x;
    const float4* x4 = reinterpret_cast<const float4*>(x);
    float4*       o4 = reinterpret_cast<float4*>(out);

    float4 v0 = x4[tid + 0 * K3_STRIDE];
    float4 v1 = x4[tid + 1 * K3_STRIDE];
    float4 v2 = x4[tid + 2 * K3_STRIDE];
    float4 v3 = x4[tid + 3 * K3_STRIDE];

    const float z0 = __ldg(&g_zbn[(tid + 0 * K3_STRIDE) / N4]);
    const float z1 = __ldg(&g_zbn[(tid + 1 * K3_STRIDE) / N4]);
    const float z2 = __ldg(&g_zbn[(tid + 2 * K3_STRIDE) / N4]);
    const float z3 = __ldg(&g_zbn[(tid + 3 * K3_STRIDE) / N4]);

    v0.x += z0; v0.y += z0; v0.z += z0; v0.w += z0;
    v1.x += z1; v1.y += z1; v1.z += z1; v1.w += z1;
    v2.x += z2; v2.y += z2; v2.z += z2; v2.w += z2;
    v3.x += z3; v3.y += z3; v3.z += z3; v3.w += z3;

    o4[tid + 0 * K3_STRIDE] = v0;
    o4[tid + 1 * K3_STRIDE] = v1;
    o4[tid + 2 * K3_STRIDE] = v2;
    o4[tid + 3 * K3_STRIDE] = v3;
}

// ---------------------------------------------------------------------------
// Inputs (metadata order):
//  0:x 1:y 2:Wq 3:Wk 4:Wv 5:Wz 6:bn_weight 7:bn_bias 8:bn_mean 9:bn_var
// ---------------------------------------------------------------------------
extern "C" void kernel_launch(void* const* d_in, const int* in_sizes, int n_in,
                              void* d_out, int out_size) {
    const float* x    = (const float*)d_in[0];
    const float* y    = (const float*)d_in[1];
    const float* Wv   = (const float*)d_in[4];
    const float* Wz   = (const float*)d_in[5];
    const float* bn_w = (const float*)d_in[6];
    const float* bn_b = (const float*)d_in[7];
    const float* bn_m = (const float*)d_in[8];
    const float* bn_v = (const float*)d_in[9];
    float* out = (float*)d_out;

    k_ysum<<<4096, 256>>>(y);                               // 32768 warps, 2 rows each
    k_proj<<<Bb, 256>>>(Wv, Wz, bn_w, bn_b, bn_m, bn_v);    // one block per batch
    k_out<<<K3_BLOCKS, K3_THREADS>>>(x, out);               // exact-tiled stream
}